// round 2
// baseline (speedup 1.0000x reference)
#include <cuda_runtime.h>
#include <cstdint>
#include <cstdio>

// Problem dims (fixed by the reference)
#define NROWS 32768
#define D_IN  512
#define D_HID 2048
#define D_OUT 512

// ---------------------------------------------------------------------------
// Scratch (no cudaMalloc allowed -> __device__ globals)
// ---------------------------------------------------------------------------
__device__ __align__(256) signed char g_xs8[NROWS * D_IN];           // 16 MB
__device__ __align__(256) signed char g_h1 [NROWS * D_HID];          // 64 MB
__device__ __align__(256) signed char g_h2 [NROWS * D_HID];          // 64 MB
__device__ __align__(256) signed char g_w1 [D_HID * D_IN];           // 1 MB
__device__ __align__(256) signed char g_w2 [D_HID * D_HID];          // 4 MB
__device__ __align__(256) signed char g_w3 [D_OUT * D_HID];          // 1 MB
__device__ float g_beta1[NROWS];
__device__ float g_beta2[NROWS];   // accumulates sum|h1| per row
__device__ float g_beta3[NROWS];   // accumulates sum|h2| per row
__device__ float g_alpha1[D_HID];
__device__ float g_alpha2[D_HID];
__device__ float g_alpha3[D_OUT];

// ---------------------------------------------------------------------------
// Small helpers
// ---------------------------------------------------------------------------
__device__ __forceinline__ unsigned smem_addr(const void* p) {
    return (unsigned)__cvta_generic_to_shared(p);
}
__device__ __forceinline__ void cp_async16(unsigned s, const void* g) {
    asm volatile("cp.async.cg.shared.global [%0], [%1], 16;" :: "r"(s), "l"(g));
}

// Zero the beta accumulators (re-run every replay: graph-capturable, deterministic)
__global__ void zero_betas() {
    int i = blockIdx.x * blockDim.x + threadIdx.x;
    if (i < NROWS) { g_beta2[i] = 0.f; g_beta3[i] = 0.f; }
}

// ---------------------------------------------------------------------------
// Pack rows of a float matrix into sign bytes (+1/-1) and per-row mean(|.|).
// One warp per row; K must be a multiple of 128. Grid sized exactly.
// ---------------------------------------------------------------------------
__global__ void pack_rows(const float* __restrict__ src,
                          signed char* __restrict__ dst,
                          float* __restrict__ scale,
                          int K, float inv) {
    int row  = (blockIdx.x * blockDim.x + threadIdx.x) >> 5;
    int lane = threadIdx.x & 31;
    const float4* s4 = (const float4*)(src + (size_t)row * K);
    char4* d4 = (char4*)(dst + (size_t)row * K);
    float sum = 0.f;
    int nv = K >> 7;             // float4 chunks per lane
    for (int j = 0; j < nv; ++j) {
        float4 v = s4[j * 32 + lane];
        sum += fabsf(v.x) + fabsf(v.y) + fabsf(v.z) + fabsf(v.w);
        char4 c;
        c.x = (v.x >= 0.f) ? 1 : -1;
        c.y = (v.y >= 0.f) ? 1 : -1;
        c.z = (v.z >= 0.f) ? 1 : -1;
        c.w = (v.w >= 0.f) ? 1 : -1;
        d4[j * 32 + lane] = c;
    }
#pragma unroll
    for (int o = 16; o; o >>= 1) sum += __shfl_xor_sync(0xffffffffu, sum, o);
    if (lane == 0) scale[row] = sum * inv;
}

// ---------------------------------------------------------------------------
// Binary GEMM:  acc[m][n] = sum_k A[m][k]*B[n][k]   (A,B are +-1 int8)
// Epilogue:     y = acc * (beta[m]*beta_mul) * alpha[n] + bias[n]
//   SIGN_OUT=1: h = prelu(y); write sign(h) bytes to sOut; atomicAdd sum|h|
//               per row into betaNext (consumed as mean via next beta_mul).
//   SIGN_OUT=0: write y (fp32) to fOut.
//
// CTA tile 128x128, BK=64 bytes, 4 warps with 64x64 warp tiles,
// mma.sync.m16n8k32.s8. THREE-stage cp.async ring (wait_group 1 in steady
// state -> each stage gets ~2 compute iterations of latency slack), padded
// smem row stride 80B (conflict-free 32-bit fragment loads).
// ---------------------------------------------------------------------------
#define NSTAGE 3

template <int SIGN_OUT>
__global__ void __launch_bounds__(128, 2)
bin_gemm(const signed char* __restrict__ A, const signed char* __restrict__ B,
         int K, int N,
         const float* __restrict__ beta, float beta_mul,
         const float* __restrict__ alpha, const float* __restrict__ bias,
         const float* __restrict__ prelu_w,
         signed char* __restrict__ sOut, float* __restrict__ betaNext,
         float* __restrict__ fOut)
{
    __shared__ __align__(16) signed char shA[NSTAGE][128 * 80];
    __shared__ __align__(16) signed char shB[NSTAGE][128 * 80];

    const int tid  = threadIdx.x;
    const int lane = tid & 31;
    const int warp = tid >> 5;
    const int wm = (warp >> 1) * 64;     // warp M offset in CTA tile
    const int wn = (warp & 1)  * 64;     // warp N offset
    const int m0 = blockIdx.y * 128;
    const int n0 = blockIdx.x * 128;

    int c[4][8][4];
#pragma unroll
    for (int i = 0; i < 4; ++i)
#pragma unroll
        for (int j = 0; j < 8; ++j)
#pragma unroll
            for (int k = 0; k < 4; ++k) c[i][j][k] = 0;

    const int rs = tid >> 2;             // staging row base (0..31)
    const int cs = (tid & 3) * 16;       // staging 16B column

    auto stage = [&](int buf, int kt) {
        const int k0 = kt * 64;
#pragma unroll
        for (int i = 0; i < 4; ++i) {
            int rr = rs + i * 32;
            cp_async16(smem_addr(&shA[buf][rr * 80 + cs]),
                       A + (size_t)(m0 + rr) * K + k0 + cs);
            cp_async16(smem_addr(&shB[buf][rr * 80 + cs]),
                       B + (size_t)(n0 + rr) * K + k0 + cs);
        }
        asm volatile("cp.async.commit_group;");
    };

    const int KT = K >> 6;

    // prologue: prefetch stages 0 .. NSTAGE-2
    stage(0, 0);
    if (KT > 1) stage(1, 1);

    const int aro = wm + (lane >> 2);
    const int bro = wn + (lane >> 2);
    const int co  = (lane & 3) * 4;

    for (int kt = 0; kt < KT; ++kt) {
        // wait for group kt. In steady state (another group still in flight
        // behind it) wait_group 1 suffices; on the last iteration drain all.
        if (kt + 1 < KT) asm volatile("cp.async.wait_group 1;");
        else             asm volatile("cp.async.wait_group 0;");
        __syncthreads();   // also guards reuse of ring slot (kt+2)%NSTAGE

        // issue the prefetch for kt+2 into the slot compute finished at kt-1
        if (kt + 2 < KT) stage((kt + 2) % NSTAGE, kt + 2);

        const signed char* sa = shA[kt % NSTAGE];
        const signed char* sb = shB[kt % NSTAGE];
#pragma unroll
        for (int kc = 0; kc < 2; ++kc) {
            const int kb = kc * 32;
            unsigned a[4][4];
#pragma unroll
            for (int mi = 0; mi < 4; ++mi) {
                const signed char* p = sa + (aro + mi * 16) * 80 + kb + co;
                a[mi][0] = *(const unsigned*)(p);
                a[mi][1] = *(const unsigned*)(p + 8 * 80);
                a[mi][2] = *(const unsigned*)(p + 16);
                a[mi][3] = *(const unsigned*)(p + 8 * 80 + 16);
            }
#pragma unroll
            for (int ni = 0; ni < 8; ++ni) {
                const signed char* p = sb + (bro + ni * 8) * 80 + kb + co;
                unsigned b0 = *(const unsigned*)(p);
                unsigned b1 = *(const unsigned*)(p + 16);
#pragma unroll
                for (int mi = 0; mi < 4; ++mi) {
                    asm volatile(
                        "mma.sync.aligned.m16n8k32.row.col.s32.s8.s8.s32 "
                        "{%0,%1,%2,%3},{%4,%5,%6,%7},{%8,%9},{%0,%1,%2,%3};"
                        : "+r"(c[mi][ni][0]), "+r"(c[mi][ni][1]),
                          "+r"(c[mi][ni][2]), "+r"(c[mi][ni][3])
                        : "r"(a[mi][0]), "r"(a[mi][1]),
                          "r"(a[mi][2]), "r"(a[mi][3]),
                          "r"(b0), "r"(b1));
                }
            }
        }
        __syncthreads();   // all warps done with slot kt%NSTAGE before next stage overwrite
    }

    // ---------------- epilogue ----------------
    const float pw = SIGN_OUT ? prelu_w[0] : 0.f;
#pragma unroll
    for (int mi = 0; mi < 4; ++mi) {
#pragma unroll
        for (int sel = 0; sel < 2; ++sel) {
            const int row = m0 + wm + mi * 16 + (lane >> 2) + sel * 8;
            const float bm = beta[row] * beta_mul;
            float asum = 0.f;
#pragma unroll
            for (int ni = 0; ni < 8; ++ni) {
                const int col = n0 + wn + ni * 8 + (lane & 3) * 2;
                const float y0 = (float)c[mi][ni][sel * 2]     * bm * alpha[col]     + bias[col];
                const float y1 = (float)c[mi][ni][sel * 2 + 1] * bm * alpha[col + 1] + bias[col + 1];
                if (SIGN_OUT) {
                    const float h0 = (y0 > 0.f) ? y0 : pw * y0;
                    const float h1 = (y1 > 0.f) ? y1 : pw * y1;
                    asum += fabsf(h0) + fabsf(h1);
                    const unsigned char s0 = (y0 >= 0.f) ? 1u : 0xFFu;  // +1 / -1
                    const unsigned char s1 = (y1 >= 0.f) ? 1u : 0xFFu;
                    const unsigned short pk = (unsigned short)(s0 | (s1 << 8));
                    *(unsigned short*)(sOut + (size_t)row * N + col) = pk;
                } else {
                    *(float2*)(fOut + (size_t)row * N + col) = make_float2(y0, y1);
                }
            }
            if (SIGN_OUT) {
                asum += __shfl_xor_sync(0xffffffffu, asum, 1);
                asum += __shfl_xor_sync(0xffffffffu, asum, 2);
                if ((lane & 3) == 0) atomicAdd(&betaNext[row], asum);
            }
        }
    }
}

// ---------------------------------------------------------------------------
// Launch: zero -> pack(x, W1..W3) -> gemm1(sign out) -> gemm2(sign out)
//         -> gemm3(fp32 out). All on default stream, graph-capturable.
// ---------------------------------------------------------------------------
extern "C" void kernel_launch(void* const* d_in, const int* in_sizes, int n_in,
                              void* d_out, int out_size) {
    const float* x  = (const float*)d_in[0];
    const float* W1 = (const float*)d_in[1];
    const float* b1 = (const float*)d_in[2];
    const float* W2 = (const float*)d_in[3];
    const float* b2 = (const float*)d_in[4];
    const float* W3 = (const float*)d_in[5];
    const float* b3 = (const float*)d_in[6];
    const float* pw = (const float*)d_in[7];
    float* out = (float*)d_out;

    void *xs8, *h1, *h2, *w1, *w2, *w3;
    void *be1, *be2, *be3, *al1, *al2, *al3;
    cudaGetSymbolAddress(&xs8, g_xs8);
    cudaGetSymbolAddress(&h1,  g_h1);
    cudaGetSymbolAddress(&h2,  g_h2);
    cudaGetSymbolAddress(&w1,  g_w1);
    cudaGetSymbolAddress(&w2,  g_w2);
    cudaGetSymbolAddress(&w3,  g_w3);
    cudaGetSymbolAddress(&be1, g_beta1);
    cudaGetSymbolAddress(&be2, g_beta2);
    cudaGetSymbolAddress(&be3, g_beta3);
    cudaGetSymbolAddress(&al1, g_alpha1);
    cudaGetSymbolAddress(&al2, g_alpha2);
    cudaGetSymbolAddress(&al3, g_alpha3);

    zero_betas<<<NROWS / 256, 256>>>();

    // one warp per row, exact grids
    pack_rows<<<NROWS / 8, 256>>>(x,  (signed char*)xs8, (float*)be1, D_IN,  1.f / D_IN);
    pack_rows<<<D_HID / 8, 256>>>(W1, (signed char*)w1,  (float*)al1, D_IN,  1.f / D_IN);
    pack_rows<<<D_HID / 8, 256>>>(W2, (signed char*)w2,  (float*)al2, D_HID, 1.f / D_HID);
    pack_rows<<<D_OUT / 8, 256>>>(W3, (signed char*)w3,  (float*)al3, D_HID, 1.f / D_HID);

    dim3 blk(128);
    dim3 g12(D_HID / 128, NROWS / 128);   // (16, 256)
    dim3 g3 (D_OUT / 128, NROWS / 128);   // (4, 256)

    // layer 1: A=sign(x) [K=512], B=sign(W1), beta1 is already the mean
    bin_gemm<1><<<g12, blk>>>((const signed char*)xs8, (const signed char*)w1,
                              D_IN, D_HID,
                              (const float*)be1, 1.f,
                              (const float*)al1, b1, pw,
                              (signed char*)h1, (float*)be2, nullptr);

    // layer 2: beta2 holds sum|h1| -> mean via beta_mul = 1/2048
    bin_gemm<1><<<g12, blk>>>((const signed char*)h1, (const signed char*)w2,
                              D_HID, D_HID,
                              (const float*)be2, 1.f / D_HID,
                              (const float*)al2, b2, pw,
                              (signed char*)h2, (float*)be3, nullptr);

    // layer 3: fp32 output
    bin_gemm<0><<<g3, blk>>>((const signed char*)h2, (const signed char*)w3,
                             D_HID, D_OUT,
                             (const float*)be3, 1.f / D_HID,
                             (const float*)al3, b3, pw,
                             nullptr, nullptr, out);
}

// round 6
// speedup vs baseline: 2.0844x; 2.0844x over previous
#include <cuda_runtime.h>
#include <cstdint>

// Problem dims (fixed by the reference)
#define NROWS 32768
#define D_IN  512
#define D_HID 2048
#define D_OUT 512
#define KW1   (D_IN  / 32)   // 16 words
#define KW2   (D_HID / 32)   // 64 words

// ---------------------------------------------------------------------------
// Scratch (__device__ globals; no cudaMalloc allowed). Bit-packed sign data:
// bit = 1  <=>  value < 0   (so sign(0) -> +1 matches the reference).
// ---------------------------------------------------------------------------
__device__ __align__(256) uint32_t g_xb [NROWS * KW1];   // 2 MB
__device__ __align__(256) uint32_t g_h1b[NROWS * KW2];   // 8 MB
__device__ __align__(256) uint32_t g_h2b[NROWS * KW2];   // 8 MB
__device__ __align__(256) uint32_t g_w1b[D_HID * KW1];   // 128 KB
__device__ __align__(256) uint32_t g_w2b[D_HID * KW2];   // 512 KB
__device__ __align__(256) uint32_t g_w3b[D_OUT * KW2];   // 128 KB
__device__ float g_beta1[NROWS];
__device__ float g_beta2[NROWS];   // accumulates sum|h1| per row
__device__ float g_beta3[NROWS];   // accumulates sum|h2| per row
__device__ float g_alpha1[D_HID];
__device__ float g_alpha2[D_HID];
__device__ float g_alpha3[D_OUT];

// ---------------------------------------------------------------------------
// Helpers
// ---------------------------------------------------------------------------
__device__ __forceinline__ uint32_t smem_u32(const void* p) {
    uint32_t a;
    asm("{ .reg .u64 t; cvta.to.shared.u64 t, %1; cvt.u32.u64 %0, t; }"
        : "=r"(a) : "l"(p));
    return a;
}
__device__ __forceinline__ void cp_async8(uint32_t s, const void* g) {
    asm volatile("cp.async.ca.shared.global [%0], [%1], 8;" :: "r"(s), "l"(g));
}

// ---------------------------------------------------------------------------
// Pack float rows -> sign bit-words + per-row mean(|.|). One warp per row.
// Optionally zeroes the two beta accumulators (folded into the x-pack so the
// launch count stays low and every replay is deterministic).
// ---------------------------------------------------------------------------
__global__ void pack_bits(const float* __restrict__ src,
                          uint32_t* __restrict__ dst,
                          float* __restrict__ scale, int K, float inv,
                          float* __restrict__ z1, float* __restrict__ z2) {
    const int row  = (blockIdx.x * blockDim.x + threadIdx.x) >> 5;
    const int lane = threadIdx.x & 31;
    const int Kw   = K >> 5;
    const float* s = src + (size_t)row * K;
    float sum = 0.f;
    uint32_t w0 = 0, w1 = 0;
    for (int w = 0; w < Kw; ++w) {
        float v = s[w * 32 + lane];                       // coalesced 128B
        sum += fabsf(v);
        uint32_t b = __ballot_sync(0xffffffffu, v < 0.f);
        if (lane == (w & 31)) { if (w < 32) w0 = b; else w1 = b; }
    }
#pragma unroll
    for (int o = 16; o; o >>= 1) sum += __shfl_xor_sync(0xffffffffu, sum, o);
    if (lane < Kw)      dst[(size_t)row * Kw + lane]      = w0;
    if (lane + 32 < Kw) dst[(size_t)row * Kw + lane + 32] = w1;
    if (lane == 0) {
        scale[row] = sum * inv;
        if (z1) { z1[row] = 0.f; z2[row] = 0.f; }
    }
}

// ---------------------------------------------------------------------------
// Popcount binary GEMM.
//   dot[m][n] = K - 2 * sum_w popc(A[m][w] ^ B[n][w])
//   y = dot * beta[m]*beta_mul * alpha[n] + bias[n]
// SIGN_OUT=1: emit sign bits of y (== sign of prelu(y)) straight into the
//             next layer's bit matrix via ballots; accumulate sum|prelu(y)|
//             per row (shuffle-reduce + 1 atomicAdd per row per N-tile).
// SIGN_OUT=0: write y as fp32.
//
// CTA tile 128x128, 256 threads, 8x8 outputs/thread. K resident in smem
// (padded row stride KW+2 words -> odd 8B-pair stride -> conflict-free
// lane-consecutive LDS.64 on the B fragments; A fragments broadcast).
// Thread map: tx = tid&15 (N), ty = tid>>4 (M).
//   rows  m0 + ty*8 + r   (r = 0..7)
//   cols  n0 + tx + 16*j  (j = 0..7)   <- strided so B rows are lane-consecutive
// ---------------------------------------------------------------------------
template <int KW, int SIGN_OUT>
__global__ void __launch_bounds__(256, 2)
bin_gemm_pc(const uint32_t* __restrict__ A, const uint32_t* __restrict__ Bm,
            int Nout,
            const float* __restrict__ beta, float beta_mul,
            const float* __restrict__ alpha, const float* __restrict__ bias,
            const float* __restrict__ prelu_w,
            uint32_t* __restrict__ bOut, float* __restrict__ betaNext,
            float* __restrict__ fOut)
{
    constexpr int PW = KW + 2;                 // padded smem row stride (words)
    extern __shared__ uint32_t sh[];
    uint32_t* As = sh;                         // [128][PW]
    uint32_t* Bs = sh + 128 * PW;              // [128][PW]

    const int tid = threadIdx.x;
    const int tx  = tid & 15;
    const int ty  = tid >> 4;
    const int m0  = blockIdx.y * 128;
    const int n0  = blockIdx.x * 128;

    // ---- stage both tiles (K fully resident; 8B cp.async chunks) ----
    {
        const uint32_t asb = smem_u32(As), bsb = smem_u32(Bs);
        constexpr int CH = KW / 2;             // 8B chunks per row
#pragma unroll
        for (int i = 0; i < (128 * CH) / 256; ++i) {
            int idx = tid + i * 256;
            int r = idx / CH, c = idx % CH;
            cp_async8(asb + (r * PW + c * 2) * 4, A  + (size_t)(m0 + r) * KW + c * 2);
            cp_async8(bsb + (r * PW + c * 2) * 4, Bm + (size_t)(n0 + r) * KW + c * 2);
        }
        asm volatile("cp.async.commit_group;");
        asm volatile("cp.async.wait_group 0;");
    }
    __syncthreads();

    // ---- main loop: 8x8 register tile, 2 k-words per step, 2x unrolled ----
    uint32_t acc[8][8];
#pragma unroll
    for (int i = 0; i < 8; ++i)
#pragma unroll
        for (int j = 0; j < 8; ++j) acc[i][j] = 0;

#pragma unroll 2
    for (int k = 0; k < KW; k += 2) {
        uint2 a2[8], b2[8];
#pragma unroll
        for (int i = 0; i < 8; ++i)
            a2[i] = *(const uint2*)&As[(ty * 8 + i) * PW + k];
#pragma unroll
        for (int j = 0; j < 8; ++j)
            b2[j] = *(const uint2*)&Bs[(tx + 16 * j) * PW + k];
#pragma unroll
        for (int i = 0; i < 8; ++i)
#pragma unroll
            for (int j = 0; j < 8; ++j)
                acc[i][j] += __popc(a2[i].x ^ b2[j].x) +
                             __popc(a2[i].y ^ b2[j].y);
    }

    // ---- epilogue ----
    const float Kf = (float)(KW * 32);
    float al[8], bi[8];
#pragma unroll
    for (int j = 0; j < 8; ++j) {
        al[j] = alpha[n0 + tx + 16 * j];
        bi[j] = bias [n0 + tx + 16 * j];
    }
    const int sh16 = tid & 16;                 // lane>=16 picks high half of ballots

    if (SIGN_OUT) {
        const float pw = prelu_w[0];
#pragma unroll 1
        for (int r = 0; r < 8; ++r) {
            const int row = m0 + ty * 8 + r;
            const float bm = beta[row] * beta_mul;
            float yv[8];
            uint32_t bal[8];
            float asum = 0.f;
#pragma unroll
            for (int j = 0; j < 8; ++j)
                yv[j] = fmaf((Kf - 2.f * (float)acc[r][j]) * bm, al[j], bi[j]);
#pragma unroll
            for (int j = 0; j < 8; ++j)
                bal[j] = __ballot_sync(0xffffffffu, yv[j] < 0.f);
#pragma unroll
            for (int j = 0; j < 8; ++j) {
                float h = yv[j] > 0.f ? yv[j] : pw * yv[j];
                asum += fabsf(h);
            }
            if (tx == 0) {                     // lanes 0 & 16: one row each
#pragma unroll
                for (int w = 0; w < 4; ++w) {
                    uint32_t word = ((bal[2 * w]      >> sh16) & 0xFFFFu) |
                                    (((bal[2 * w + 1] >> sh16) & 0xFFFFu) << 16);
                    bOut[(size_t)row * (Nout >> 5) + (n0 >> 5) + w] = word;
                }
            }
#pragma unroll
            for (int o = 1; o < 16; o <<= 1)
                asum += __shfl_xor_sync(0xffffffffu, asum, o);
            if (tx == 0) atomicAdd(&betaNext[row], asum);
        }
    } else {
#pragma unroll 1
        for (int r = 0; r < 8; ++r) {
            const int row = m0 + ty * 8 + r;
            const float bm = beta[row] * beta_mul;
            float* o = fOut + (size_t)row * Nout + n0 + tx;
#pragma unroll
            for (int j = 0; j < 8; ++j)
                o[16 * j] = fmaf((Kf - 2.f * (float)acc[r][j]) * bm, al[j], bi[j]);
        }
    }
}

// ---------------------------------------------------------------------------
// Launch: pack(x: also zeroes betas) -> pack(W1..W3) -> gemm1 -> gemm2 -> gemm3
// ---------------------------------------------------------------------------
extern "C" void kernel_launch(void* const* d_in, const int* in_sizes, int n_in,
                              void* d_out, int out_size) {
    const float* x  = (const float*)d_in[0];
    const float* W1 = (const float*)d_in[1];
    const float* b1 = (const float*)d_in[2];
    const float* W2 = (const float*)d_in[3];
    const float* b2 = (const float*)d_in[4];
    const float* W3 = (const float*)d_in[5];
    const float* b3 = (const float*)d_in[6];
    const float* pw = (const float*)d_in[7];
    float* out = (float*)d_out;

    void *xb, *h1, *h2, *w1, *w2, *w3, *be1, *be2, *be3, *al1, *al2, *al3;
    cudaGetSymbolAddress(&xb,  g_xb);
    cudaGetSymbolAddress(&h1,  g_h1b);
    cudaGetSymbolAddress(&h2,  g_h2b);
    cudaGetSymbolAddress(&w1,  g_w1b);
    cudaGetSymbolAddress(&w2,  g_w2b);
    cudaGetSymbolAddress(&w3,  g_w3b);
    cudaGetSymbolAddress(&be1, g_beta1);
    cudaGetSymbolAddress(&be2, g_beta2);
    cudaGetSymbolAddress(&be3, g_beta3);
    cudaGetSymbolAddress(&al1, g_alpha1);
    cudaGetSymbolAddress(&al2, g_alpha2);
    cudaGetSymbolAddress(&al3, g_alpha3);

    const int smem1 = 2 * 128 * (KW1 + 2) * 4;   // 18432 B
    const int smem2 = 2 * 128 * (KW2 + 2) * 4;   // 67584 B
    cudaFuncSetAttribute(bin_gemm_pc<KW1, 1>, cudaFuncAttributeMaxDynamicSharedMemorySize, smem1);
    cudaFuncSetAttribute(bin_gemm_pc<KW2, 1>, cudaFuncAttributeMaxDynamicSharedMemorySize, smem2);
    cudaFuncSetAttribute(bin_gemm_pc<KW2, 0>, cudaFuncAttributeMaxDynamicSharedMemorySize, smem2);

    // packs (x-pack also zeroes beta2/beta3)
    pack_bits<<<NROWS / 8, 256>>>(x,  (uint32_t*)xb, (float*)be1, D_IN,  1.f / D_IN,
                                  (float*)be2, (float*)be3);
    pack_bits<<<D_HID / 8, 256>>>(W1, (uint32_t*)w1, (float*)al1, D_IN,  1.f / D_IN,
                                  nullptr, nullptr);
    pack_bits<<<D_HID / 8, 256>>>(W2, (uint32_t*)w2, (float*)al2, D_HID, 1.f / D_HID,
                                  nullptr, nullptr);
    pack_bits<<<D_OUT / 8, 256>>>(W3, (uint32_t*)w3, (float*)al3, D_HID, 1.f / D_HID,
                                  nullptr, nullptr);

    dim3 blk(256);
    dim3 g12(D_HID / 128, NROWS / 128);   // (16, 256)
    dim3 g3 (D_OUT / 128, NROWS / 128);   // (4, 256)

    // layer 1: A = sign(x) bits [K=512], beta1 already the mean
    bin_gemm_pc<KW1, 1><<<g12, blk, smem1>>>((const uint32_t*)xb, (const uint32_t*)w1,
        D_HID, (const float*)be1, 1.f, (const float*)al1, b1, pw,
        (uint32_t*)h1, (float*)be2, nullptr);

    // layer 2: beta2 holds sum|h1| -> mean via beta_mul = 1/2048
    bin_gemm_pc<KW2, 1><<<g12, blk, smem2>>>((const uint32_t*)h1, (const uint32_t*)w2,
        D_HID, (const float*)be2, 1.f / D_HID, (const float*)al2, b2, pw,
        (uint32_t*)h2, (float*)be3, nullptr);

    // layer 3: fp32 output
    bin_gemm_pc<KW2, 0><<<g3, blk, smem2>>>((const uint32_t*)h2, (const uint32_t*)w3,
        D_OUT, (const float*)be3, 1.f / D_HID, (const float*)al3, b3, pw,
        nullptr, nullptr, out);
}